// round 16
// baseline (speedup 1.0000x reference)
#include <cuda_runtime.h>
#include <cuda_fp16.h>
#include <cstdint>
#include <math.h>

#define BATCH 2048
#define UNITS 1024
#define GATES 4096
#define OUTU 256
#define NCOMB 4352            // [Wc | Wd]
#define STEPS 96
#define K0 1280               // step-0 K: [x | h]
#define LDO (STEPS * OUTU)
#define LOSCALE 2048.0f
#define INV_LOSCALE (1.0f / 2048.0f)

// persistent-schedule constants
#define NWS_T 68              // wsplit tickets (68 x 65536 = 1024*4352 exactly)
#define T0 1024               // step-0 tiles (64 gate n-tiles x 16 m-rows)
#define TSZ 1088              // tiles per step 1..95 (1024 gates + 64 preds)
#define TTOTAL (NWS_T + T0 + 95 * TSZ + 64)
#define NCTAS 296             // 2 CTAs/SM x 148 SMs

// ------------------------------ device scratch ------------------------------
__device__ __align__(256) float g_Wcd[UNITS * NCOMB];   // fp32 combined weights
__device__ __align__(256) float g_bcd[NCOMB];           // combined bias (gate-interleaved + pred)
__device__ __align__(256) float g_b0i[GATES];           // step0 bias (gate-interleaved)
__device__ __align__(256) float g_cf[BATCH * UNITS];    // cell state, FRAGMENT layout
__device__ __align__(256) __half g_h0[BATCH * UNITS];   // h ping-pong (plain fp16)
__device__ __align__(256) __half g_h1[BATCH * UNITS];
__device__ __align__(256) __half g_wthi[(size_t)NCOMB * UNITS];  // W^T hi, interleaved rows
__device__ __align__(256) __half g_wtlo[(size_t)NCOMB * UNITS];  // W^T lo*2048
__device__ __align__(256) __half g_w0hi[(size_t)GATES * K0];     // step0 W^T hi
__device__ __align__(256) __half g_w0lo[(size_t)GATES * K0];     // step0 W^T lo*2048
__device__ __align__(256) __half g_a0[(size_t)BATCH * K0];       // step0 A=[x|h] fp16
// [0]=ticket, [1]=wsplit-done count, [2..] = per-(step,mrow) gate completions
__device__ int g_sync[2 + STEPS * 16];

__device__ __forceinline__ int icol(int n) {            // gate interleave: unit*4+gate
    return (n < GATES) ? ((n & 1023) * 4 + (n >> 10)) : n;
}

// ------------------------------ PTX helpers ---------------------------------
__device__ __forceinline__ uint32_t smem_u32(const void* p) {
    uint32_t a;
    asm("{ .reg .u64 t; cvta.to.shared.u64 t, %1; cvt.u32.u64 %0, t; }" : "=r"(a) : "l"(p));
    return a;
}
__device__ __forceinline__ uint32_t swz(uint32_t off) { return off ^ ((off >> 3) & 0x70); }
__device__ __forceinline__ void cpa16(uint32_t dst, const void* src) {
    asm volatile("cp.async.cg.shared.global [%0], [%1], 16;" :: "r"(dst), "l"(src) : "memory");
}
#define CP_COMMIT()  asm volatile("cp.async.commit_group;" ::: "memory")
#define CP_WAIT(n)   asm volatile("cp.async.wait_group %0;" :: "n"(n) : "memory")

__device__ __forceinline__ void ldsm4(uint32_t* r, uint32_t addr) {
    asm volatile("ldmatrix.sync.aligned.m8n8.x4.shared.b16 {%0,%1,%2,%3}, [%4];"
        : "=r"(r[0]), "=r"(r[1]), "=r"(r[2]), "=r"(r[3]) : "r"(addr));
}
__device__ __forceinline__ void mma_f32(float* d, const uint32_t* a, uint32_t b0, uint32_t b1) {
    asm volatile("mma.sync.aligned.m16n8k16.row.col.f32.f16.f16.f32 "
        "{%0,%1,%2,%3}, {%4,%5,%6,%7}, {%8,%9}, {%0,%1,%2,%3};"
        : "+f"(d[0]), "+f"(d[1]), "+f"(d[2]), "+f"(d[3])
        : "r"(a[0]), "r"(a[1]), "r"(a[2]), "r"(a[3]), "r"(b0), "r"(b1));
}
__device__ __forceinline__ void mma_f16(uint32_t* d, const uint32_t* a, uint32_t b0, uint32_t b1) {
    asm volatile("mma.sync.aligned.m16n8k16.row.col.f16.f16.f16.f16 "
        "{%0,%1}, {%2,%3,%4,%5}, {%6,%7}, {%0,%1};"
        : "+r"(d[0]), "+r"(d[1])
        : "r"(a[0]), "r"(a[1]), "r"(a[2]), "r"(a[3]), "r"(b0), "r"(b1));
}
// fast sigmoid / tanh via HW exp (error ~2^-17, negligible vs fp16-h noise)
__device__ __forceinline__ float fsig(float x) {
    return 1.0f / (1.0f + __expf(-x));
}
__device__ __forceinline__ float ftanh(float x) {
    float e = __expf(2.0f * x);
    return __fdividef(e - 1.0f, e + 1.0f);
}

// ------------------------------ tile pipeline --------------------------------
// z = A(fp16) @ [Whi + Wlo/2048]^T : main fp32-acc + one fp16-acc correction.
// Tile 128(M)x64(N), 256 thr (4m x 2n warps, 32x32 each), KC=64,
// 3-stage cp.async pipeline (32KB/stage, 96KB/CTA -> 2 CTAs/SM).
// R4/R10-validated skeleton: DO NOT restructure the mainloop.
#define KC 64
#define OFF_AHI 0
#define OFF_BHI 16384
#define OFF_BLO 24576
#define STAGE_BYTES 32768
#define SMEM_TOTAL (3 * STAGE_BYTES)

__device__ __forceinline__ void load_chunk(
    uint32_t sb, int tid,
    const __half* __restrict__ a,
    const __half* __restrict__ bhi, const __half* __restrict__ blo,
    int r0, int n0, int K, int kc)
{
    const int kcol = kc * KC;
    #pragma unroll
    for (int i = 0; i < 4; ++i) {              // A: 128 rows x 8 chunks of 16B
        int q = tid + i * 256;
        int row = q >> 3, jj = q & 7;
        uint32_t so = swz(row * 128 + jj * 16);
        size_t ga = (size_t)(r0 + row) * K + kcol + jj * 8;
        cpa16(sb + OFF_AHI + so, a + ga);
    }
    #pragma unroll
    for (int i = 0; i < 2; ++i) {              // B: 64 rows x 8 chunks of 16B
        int q = tid + i * 256;
        int row = q >> 3, jj = q & 7;
        uint32_t so = swz(row * 128 + jj * 16);
        size_t gb = (size_t)(n0 + row) * K + kcol + jj * 8;
        cpa16(sb + OFF_BHI + so, bhi + gb);
        cpa16(sb + OFF_BLO + so, blo + gb);
    }
    CP_COMMIT();
}

__device__ __forceinline__ void load_b_chunk(
    uint32_t sb, int tid,
    const __half* __restrict__ bhi, const __half* __restrict__ blo,
    int n0, int K, int kc)
{
    const int kcol = kc * KC;
    #pragma unroll
    for (int i = 0; i < 2; ++i) {
        int q = tid + i * 256;
        int row = q >> 3, jj = q & 7;
        uint32_t so = swz(row * 128 + jj * 16);
        size_t gb = (size_t)(n0 + row) * K + kcol + jj * 8;
        cpa16(sb + OFF_BHI + so, bhi + gb);
        cpa16(sb + OFF_BLO + so, blo + gb);
    }
    CP_COMMIT();
}
__device__ __forceinline__ void load_a_chunk(
    uint32_t sb, int tid, const __half* __restrict__ a,
    int r0, int K, int kc)
{
    const int kcol = kc * KC;
    #pragma unroll
    for (int i = 0; i < 4; ++i) {
        int q = tid + i * 256;
        int row = q >> 3, jj = q & 7;
        uint32_t so = swz(row * 128 + jj * 16);
        size_t ga = (size_t)(r0 + row) * K + kcol + jj * 8;
        cpa16(sb + OFF_AHI + so, a + ga);
    }
    CP_COMMIT();
}

// One 128x64 tile: B preload -> dependency spin -> A preload -> mainloop ->
// fused LSTM / pred epilogue. Body identical to R15.
__device__ __forceinline__ void tile_work(
    const __half* __restrict__ a,
    const __half* __restrict__ bhi, const __half* __restrict__ blo,
    int K, const float* __restrict__ bias, int n, int mrow, int t,
    float* __restrict__ outp, __half* __restrict__ hout,
    uint32_t sbase, int tid, volatile int* depcnt, int deptarget)
{
    const int lane = tid & 31, w = tid >> 5;
    const int wm = w & 3, wn = w >> 2;             // 4 (m) x 2 (n) warps
    const int r0 = mrow * 128;
    const int n0 = n * 64;
    const int nch = K / KC;

    float dm[2][4][4];
    uint32_t dc[2][4][2];
    #pragma unroll
    for (int mi = 0; mi < 2; ++mi)
        #pragma unroll
        for (int nj = 0; nj < 4; ++nj) {
            #pragma unroll
            for (int q = 0; q < 4; ++q) dm[mi][nj][q] = 0.0f;
            dc[mi][nj][0] = 0u; dc[mi][nj][1] = 0u;
        }

    // B (constant weights) first; spin on producer row-block; then A.
    load_b_chunk(sbase + 0 * STAGE_BYTES, tid, bhi, blo, n0, K, 0);
    load_b_chunk(sbase + 1 * STAGE_BYTES, tid, bhi, blo, n0, K, 1);
    if (depcnt != nullptr) {
        if (tid == 0) {
            while (*depcnt < deptarget) __nanosleep(128);
            __threadfence();
        }
        __syncthreads();
    }
    load_a_chunk(sbase + 0 * STAGE_BYTES, tid, a, r0, K, 0);
    load_a_chunk(sbase + 1 * STAGE_BYTES, tid, a, r0, K, 1);

    const int lr = lane & 7, sel = lane >> 3;

    for (int kc = 0; kc < nch; ++kc) {
        if (kc + 2 < nch) {
            load_chunk(sbase + ((kc + 2) % 3) * STAGE_BYTES, tid,
                       a, bhi, blo, r0, n0, K, kc + 2);
            CP_WAIT(2);
        } else if (kc + 1 < nch) {
            CP_WAIT(1);
        } else {
            CP_WAIT(0);
        }
        __syncthreads();
        const uint32_t sb = sbase + (kc % 3) * STAGE_BYTES;

        #pragma unroll
        for (int k16 = 0; k16 < 4; ++k16) {
            uint32_t ah[2][4], bh[2][4], bl[2][4];
            #pragma unroll
            for (int mi = 0; mi < 2; ++mi) {
                int row = wm * 32 + mi * 16 + lr + (sel & 1) * 8;
                int kbe = (k16 * 16 + (sel >> 1) * 8) * 2;
                ldsm4(ah[mi], sb + OFF_AHI + swz(row * 128 + kbe));
            }
            #pragma unroll
            for (int njp = 0; njp < 2; ++njp) {
                int nrow = wn * 32 + njp * 16 + lr + (sel >> 1) * 8;
                int kbe = (k16 * 16 + (sel & 1) * 8) * 2;
                uint32_t off = swz(nrow * 128 + kbe);
                ldsm4(bh[njp], sb + OFF_BHI + off);
                ldsm4(bl[njp], sb + OFF_BLO + off);
            }
            #pragma unroll
            for (int mi = 0; mi < 2; ++mi)
                #pragma unroll
                for (int nj = 0; nj < 4; ++nj)
                    mma_f32(dm[mi][nj], ah[mi],
                            bh[nj >> 1][(nj & 1) * 2], bh[nj >> 1][(nj & 1) * 2 + 1]);
            #pragma unroll
            for (int mi = 0; mi < 2; ++mi)
                #pragma unroll
                for (int nj = 0; nj < 4; ++nj)
                    mma_f16(dc[mi][nj], ah[mi],
                            bl[nj >> 1][(nj & 1) * 2], bl[nj >> 1][(nj & 1) * 2 + 1]);
        }
        __syncthreads();
    }

    // ---------------- epilogue ----------------
    const bool isPred = (n0 >= GATES);
    const int qr = lane >> 2, t4 = lane & 3, qc = t4 * 2;
    const bool evenT = ((t4 & 1) == 0);
    const int etid = w * 16 + qr * 2 + (t4 >> 1);            // [0,128)
    const size_t cbase =
        (((size_t)mrow * 64 + (size_t)n) * 128 + (size_t)etid) * 16;

    #pragma unroll
    for (int mi = 0; mi < 2; ++mi) {
        #pragma unroll
        for (int half = 0; half < 2; ++half) {
            const int r = r0 + wm * 32 + mi * 16 + qr + half * 8;
            float4 ca4;
            float* ca = &ca4.x;
            if (!isPred && evenT)
                ca4 = __ldcg(reinterpret_cast<const float4*>(
                    g_cf + cbase + mi * 8 + half * 4));     // L2 (L1 not coherent in-kernel)
            #pragma unroll
            for (int nj = 0; nj < 4; ++nj) {
                const int c = wn * 32 + nj * 8 + qc;
                __half2 hc = *reinterpret_cast<__half2*>(&dc[mi][nj][half]);
                float zx = dm[mi][nj][half * 2 + 0]
                         + INV_LOSCALE * __half2float(__low2half(hc)) + bias[n0 + c];
                float zy = dm[mi][nj][half * 2 + 1]
                         + INV_LOSCALE * __half2float(__high2half(hc)) + bias[n0 + c + 1];
                if (isPred) {
                    float2 v = make_float2(zx, zy);
                    *reinterpret_cast<float2*>(
                        outp + (size_t)r * LDO + (size_t)(t - 1) * OUTU + (n0 - GATES) + c) = v;
                } else {
                    // even t4 holds (zi,zf), odd holds (zg,zo) of the same unit
                    float ox = __shfl_xor_sync(0xffffffffu, zx, 1);
                    float oy = __shfl_xor_sync(0xffffffffu, zy, 1);
                    if (evenT) {
                        const int u = ((n0 + c) >> 2);
                        const size_t off = (size_t)r * UNITS + u;
                        float ig = fsig(zx);
                        float fg = fsig(zy);
                        float gg = ftanh(ox);
                        float og = fsig(oy);
                        float cn = fg * ca[nj] + ig * gg;
                        ca[nj] = cn;
                        hout[off] = __float2half_rn(og * ftanh(cn));
                    }
                }
            }
            if (!isPred && evenT)
                __stcg(reinterpret_cast<float4*>(g_cf + cbase + mi * 8 + half * 4), ca4);
        }
    }
}

// ------------------------------ persistent kernel ----------------------------
// Tickets: [0, NWS_T) wsplit (overlaps step 0) | step-0 tiles | steps 1..95
// (gates first, preds trail) | final preds. Tiles with B = g_wt gate on the
// wsplit counter before their B preload.
__global__ __launch_bounds__(256, 2)
void pbgemm(float* __restrict__ outp)
{
    extern __shared__ __align__(1024) char smem[];
    const uint32_t sbase = smem_u32(smem);
    const int tid = threadIdx.x;
    __shared__ int s_id;

    for (;;) {
        if (tid == 0) s_id = atomicAdd(&g_sync[0], 1);
        __syncthreads();
        const int id = s_id;
        if (id >= TTOTAL) break;

        if (id < NWS_T) {
            // wsplit ticket: transpose+interleave+fp16-split 65536 elements
            const int base = id * 65536;
            for (int e = tid; e < 65536; e += 256) {
                int idx = base + e;
                int k = idx / NCOMB, n = idx - k * NCOMB;
                float v = g_Wcd[idx];
                __half hi = __float2half_rn(v);
                size_t o = (size_t)icol(n) * UNITS + k;
                g_wthi[o] = hi;
                g_wtlo[o] = __float2half_rn((v - __half2float(hi)) * LOSCALE);
            }
            __threadfence();
            __syncthreads();
            if (tid == 0) atomicAdd(&g_sync[1], 1);
            continue;
        }

        const int tk = id - NWS_T;
        const __half *A, *BH, *BL;
        const float* bias;
        __half* hout;
        int K, n, mrow, t;
        volatile int* dep = nullptr;
        int tgt = 0;

        if (tk < T0) {                                   // step 0: gates only
            t = 0; mrow = tk >> 6; n = tk & 63;
            A = g_a0; BH = g_w0hi; BL = g_w0lo; K = K0;
            bias = g_b0i; hout = g_h1;
        } else if (tk < T0 + 95 * TSZ) {                 // steps 1..95
            int q = tk - T0;
            t = 1 + q / TSZ;
            int rem = q - (t - 1) * TSZ;
            if (rem < 1024) {                            // gates first (critical)
                mrow = rem >> 6; n = rem & 63;
            } else {                                     // preds trail the step
                int r2 = rem - 1024;
                mrow = r2 >> 2; n = 64 + (r2 & 3);
            }
            A = (t & 1) ? g_h1 : g_h0;                   // hb[t&1]
            hout = ((t + 1) & 1) ? g_h1 : g_h0;          // hb[(t+1)&1]
            BH = g_wthi; BL = g_wtlo; K = UNITS; bias = g_bcd;
            dep = (volatile int*)&g_sync[2 + (t - 1) * 16 + mrow];
            tgt = 64;                                    // gate tiles only
        } else {                                         // final pred_95 tiles
            int rem = tk - (T0 + 95 * TSZ);
            t = STEPS; mrow = rem >> 2; n = 64 + (rem & 3);
            A = g_h0;                                    // h_96 = hb[0]
            hout = g_h1;                                 // unused (pred only)
            BH = g_wthi; BL = g_wtlo; K = UNITS; bias = g_bcd;
            dep = (volatile int*)&g_sync[2 + 95 * 16 + mrow];
            tgt = 64;
        }

        // B = g_wt for all tiles beyond step 0: gate on wsplit completion
        // BEFORE the B preload inside tile_work.
        if (tk >= T0) {
            if (tid == 0) {
                while (((volatile int*)g_sync)[1] < NWS_T) __nanosleep(128);
                __threadfence();
            }
            __syncthreads();
        }

        tile_work(A, BH, BL, K, bias, n, mrow, t, outp, hout,
                  sbase, tid, dep, tgt);

        __threadfence();
        __syncthreads();
        if (tid == 0 && t < STEPS && n < 64)             // gate tiles signal
            atomicAdd(&g_sync[2 + t * 16 + mrow], 1);
    }
}

// ------------------------------ fused prep kernel ----------------------------
// All mutually-independent prep work in ONE launch (runs concurrently):
// [0,256): Wc = Wd@Wk + Wr (fp32 GEMM, writes g_Wcd cols 0..4095)
// [256,273): combined bias | [273,1297): copy_wd (g_Wcd cols 4096+)
// then w0split | a0split | c_init.  wsplit (needs g_Wcd) lives in pbgemm.
#define PA_GEMM 256
#define PA_BIAS 17
#define PA_CW 1024
#define PA_W0 20480
#define PA_A0 10240
#define PA_CI 8192
#define PA_TOTAL (PA_GEMM + PA_BIAS + PA_CW + PA_W0 + PA_A0 + PA_CI)

__global__ __launch_bounds__(256)
void prep_all(const float* __restrict__ x0, const float* __restrict__ h0,
              const float* __restrict__ c0, const float* __restrict__ Wk,
              const float* __restrict__ Wr, const float* __restrict__ b,
              const float* __restrict__ Wd, const float* __restrict__ bd) {
    __shared__ float As[8][128];
    __shared__ float Bs[8][128];
    const int blk = blockIdx.x;
    const int tid = threadIdx.x;

    if (blk < PA_GEMM) {
        // fp32 GEMM: g_Wcd[:,0:4096] = Wd[1024,256] @ Wk[256,4096] + Wr
        const int tx = tid & 15, ty = tid >> 4;
        const int col0 = (blk & 31) * 128, row0 = (blk >> 5) * 128;
        float acc[8][8];
        #pragma unroll
        for (int i = 0; i < 8; ++i)
            #pragma unroll
            for (int j = 0; j < 8; ++j) acc[i][j] = 0.0f;
        const int arow = tid >> 1, acol = (tid & 1) << 2;
        const int brow = tid >> 5, bcol = (tid & 31) << 2;
        const float* Arow = Wd + (size_t)(row0 + arow) * OUTU + acol;
        const float* Brow = Wk + (size_t)brow * GATES + col0 + bcol;
        for (int k0 = 0; k0 < 256; k0 += 8) {
            float4 av = *reinterpret_cast<const float4*>(Arow + k0);
            float4 bv = *reinterpret_cast<const float4*>(Brow + (size_t)k0 * GATES);
            As[acol + 0][arow] = av.x; As[acol + 1][arow] = av.y;
            As[acol + 2][arow] = av.z; As[acol + 3][arow] = av.w;
            *reinterpret_cast<float4*>(&Bs[brow][bcol]) = bv;
            __syncthreads();
            #pragma unroll
            for (int k = 0; k < 8; ++k) {
                float a[8], bb[8];
                #pragma unroll
                for (int i = 0; i < 8; ++i) a[i] = As[k][ty * 8 + i];
                #pragma unroll
                for (int j = 0; j < 8; ++j) bb[j] = Bs[k][tx * 8 + j];
                #pragma unroll
                for (int i = 0; i < 8; ++i)
                    #pragma unroll
                    for (int j = 0; j < 8; ++j)
                        acc[i][j] = fmaf(a[i], bb[j], acc[i][j]);
            }
            __syncthreads();
        }
        const int gcol = col0 + tx * 8;
        #pragma unroll
        for (int i = 0; i < 8; ++i) {
            int r = row0 + ty * 8 + i;
            #pragma unroll
            for (int j = 0; j < 8; j += 4) {
                float4 v = make_float4(acc[i][j], acc[i][j+1], acc[i][j+2], acc[i][j+3]);
                float4 a4 = *reinterpret_cast<const float4*>(
                    Wr + (size_t)r * GATES + gcol + j);
                v.x += a4.x; v.y += a4.y; v.z += a4.z; v.w += a4.w;
                *reinterpret_cast<float4*>(g_Wcd + (size_t)r * NCOMB + gcol + j) = v;
            }
        }
    } else if (blk < PA_GEMM + PA_BIAS) {
        int j = (blk - PA_GEMM) * 256 + tid;
        if (j < GATES) {
            float s = b[j];
            #pragma unroll 4
            for (int k = 0; k < 256; ++k)
                s += bd[k] * Wk[(size_t)k * GATES + j];
            g_bcd[icol(j)] = s;
            g_b0i[icol(j)] = b[j];
        } else if (j < NCOMB) {
            g_bcd[j] = bd[j - GATES];
        }
    } else if (blk < PA_GEMM + PA_BIAS + PA_CW) {
        int idx = (blk - PA_GEMM - PA_BIAS) * 256 + tid;
        if (idx < UNITS * OUTU) {
            int r = idx / OUTU, c = idx % OUTU;
            g_Wcd[(size_t)r * NCOMB + GATES + c] = Wd[idx];
        }
    } else if (blk < PA_GEMM + PA_BIAS + PA_CW + PA_W0) {
        int idx = (blk - PA_GEMM - PA_BIAS - PA_CW) * 256 + tid;  // GATES*K0
        int n = idx & (GATES - 1);
        int k = idx >> 12;
        float v = (k < 256) ? Wk[(size_t)k * GATES + n]
                            : Wr[(size_t)(k - 256) * GATES + n];
        __half hi = __float2half_rn(v);
        size_t o = (size_t)icol(n) * K0 + k;
        g_w0hi[o] = hi;
        g_w0lo[o] = __float2half_rn((v - __half2float(hi)) * LOSCALE);
    } else if (blk < PA_GEMM + PA_BIAS + PA_CW + PA_W0 + PA_A0) {
        int idx = (blk - PA_GEMM - PA_BIAS - PA_CW - PA_W0) * 256 + tid;  // BATCH*K0
        int r = idx / K0, k = idx - r * K0;
        float v = (k < 256) ? x0[(size_t)r * 256 + k] : h0[(size_t)r * UNITS + (k - 256)];
        g_a0[idx] = __float2half_rn(v);
    } else {
        int L = (blk - PA_GEMM - PA_BIAS - PA_CW - PA_W0 - PA_A0) * 256 + tid;
        int mt = L >> 17;            // 64 nt * 2048 per m-tile
        int rem = L & 131071;
        int nt = rem >> 11;          // 2048 per n-tile
        int rem2 = rem & 2047;
        int etid = rem2 >> 4, pos = rem2 & 15;
        int ww = etid >> 4, q = etid & 15;
        int qr = q >> 1, th = q & 1;
        int wm = ww & 3, wn = ww >> 2;
        int mi = pos >> 3, half = (pos >> 2) & 1, nj = pos & 3;
        int r = mt * 128 + wm * 32 + mi * 16 + qr + half * 8;
        int u = nt * 16 + wn * 8 + nj * 2 + th;
        g_cf[L] = c0[(size_t)r * UNITS + u];
    }
}

// ------------------------------ launch ---------------------------------------
extern "C" void kernel_launch(void* const* d_in, const int* in_sizes, int n_in,
                              void* d_out, int out_size) {
    const float* x0 = (const float*)d_in[0];
    const float* h0 = (const float*)d_in[1];
    const float* c0 = (const float*)d_in[2];
    const float* Wk = (const float*)d_in[3];
    const float* Wr = (const float*)d_in[4];
    const float* b  = (const float*)d_in[5];
    const float* Wd = (const float*)d_in[6];
    const float* bd = (const float*)d_in[7];
    float* out = (float*)d_out;

    cudaFuncSetAttribute(pbgemm, cudaFuncAttributeMaxDynamicSharedMemorySize, SMEM_TOTAL);

    int* pSync;
    cudaGetSymbolAddress((void**)&pSync, g_sync);

    // reset persistent-schedule state (graph-replay-safe, deterministic)
    cudaMemsetAsync(pSync, 0, sizeof(int) * (2 + STEPS * 16), 0);

    // ALL independent prep in one concurrent launch (GEMM blocks first)
    prep_all<<<PA_TOTAL, 256>>>(x0, h0, c0, Wk, Wr, b, Wd, bd);

    // everything else: wsplit tickets + all 97 steps, one persistent launch
    pbgemm<<<NCTAS, 256, SMEM_TOTAL>>>(out);
}

// round 17
// speedup vs baseline: 1.0340x; 1.0340x over previous
#include <cuda_runtime.h>
#include <cuda_fp16.h>
#include <cstdint>
#include <math.h>

#define BATCH 2048
#define UNITS 1024
#define GATES 4096
#define OUTU 256
#define NCOMB 4352            // [Wc | Wd]
#define STEPS 96
#define K0 1280               // step-0 K: [x | h]
#define LDO (STEPS * OUTU)
#define LOSCALE 2048.0f
#define INV_LOSCALE (1.0f / 2048.0f)

// persistent-schedule constants
#define T0 1024               // step-0 tiles (64 gate n-tiles x 16 m-rows)
#define TSZ 1088              // tiles per step 1..95 (1024 gates + 64 preds)
#define TTOTAL (T0 + 95 * TSZ + 64)   // + final 64 pred tiles
#define NCTAS 296             // 2 CTAs/SM x 148 SMs

// ------------------------------ device scratch ------------------------------
__device__ __align__(256) float g_Wcd[UNITS * NCOMB];   // fp32 combined weights
__device__ __align__(256) float g_bcd[NCOMB];           // combined bias (gate-interleaved + pred)
__device__ __align__(256) float g_b0i[GATES];           // step0 bias (gate-interleaved)
__device__ __align__(256) float g_cf[BATCH * UNITS];    // cell state, FRAGMENT layout
__device__ __align__(256) __half g_h0[BATCH * UNITS];   // h ping-pong (plain fp16)
__device__ __align__(256) __half g_h1[BATCH * UNITS];
__device__ __align__(256) __half g_wthi[(size_t)NCOMB * UNITS];  // W^T hi, interleaved rows
__device__ __align__(256) __half g_wtlo[(size_t)NCOMB * UNITS];  // W^T lo*2048
__device__ __align__(256) __half g_w0hi[(size_t)GATES * K0];     // step0 W^T hi
__device__ __align__(256) __half g_w0lo[(size_t)GATES * K0];     // step0 W^T lo*2048
__device__ __align__(256) __half g_a0[(size_t)BATCH * K0];       // step0 A=[x|h] fp16
__device__ int g_ticket;                                // global tile ticket
__device__ int g_cnt[STEPS * 16];                       // per-(step, m-row) GATE completions

__device__ __forceinline__ int icol(int n) {            // gate interleave: unit*4+gate
    return (n < GATES) ? ((n & 1023) * 4 + (n >> 10)) : n;
}

// ------------------------------ PTX helpers ---------------------------------
__device__ __forceinline__ uint32_t smem_u32(const void* p) {
    uint32_t a;
    asm("{ .reg .u64 t; cvta.to.shared.u64 t, %1; cvt.u32.u64 %0, t; }" : "=r"(a) : "l"(p));
    return a;
}
__device__ __forceinline__ uint32_t swz(uint32_t off) { return off ^ ((off >> 3) & 0x70); }
__device__ __forceinline__ void cpa16(uint32_t dst, const void* src) {
    asm volatile("cp.async.cg.shared.global [%0], [%1], 16;" :: "r"(dst), "l"(src) : "memory");
}
#define CP_COMMIT()  asm volatile("cp.async.commit_group;" ::: "memory")
#define CP_WAIT(n)   asm volatile("cp.async.wait_group %0;" :: "n"(n) : "memory")

__device__ __forceinline__ void ldsm4(uint32_t* r, uint32_t addr) {
    asm volatile("ldmatrix.sync.aligned.m8n8.x4.shared.b16 {%0,%1,%2,%3}, [%4];"
        : "=r"(r[0]), "=r"(r[1]), "=r"(r[2]), "=r"(r[3]) : "r"(addr));
}
__device__ __forceinline__ void mma_f32(float* d, const uint32_t* a, uint32_t b0, uint32_t b1) {
    asm volatile("mma.sync.aligned.m16n8k16.row.col.f32.f16.f16.f32 "
        "{%0,%1,%2,%3}, {%4,%5,%6,%7}, {%8,%9}, {%0,%1,%2,%3};"
        : "+f"(d[0]), "+f"(d[1]), "+f"(d[2]), "+f"(d[3])
        : "r"(a[0]), "r"(a[1]), "r"(a[2]), "r"(a[3]), "r"(b0), "r"(b1));
}
__device__ __forceinline__ void mma_f16(uint32_t* d, const uint32_t* a, uint32_t b0, uint32_t b1) {
    asm volatile("mma.sync.aligned.m16n8k16.row.col.f16.f16.f16.f16 "
        "{%0,%1}, {%2,%3,%4,%5}, {%6,%7}, {%0,%1};"
        : "+r"(d[0]), "+r"(d[1])
        : "r"(a[0]), "r"(a[1]), "r"(a[2]), "r"(a[3]), "r"(b0), "r"(b1));
}
// fast sigmoid / tanh via HW exp (error ~2^-17, negligible vs fp16-h noise)
__device__ __forceinline__ float fsig(float x) {
    return 1.0f / (1.0f + __expf(-x));
}
__device__ __forceinline__ float ftanh(float x) {
    float e = __expf(2.0f * x);
    return __fdividef(e - 1.0f, e + 1.0f);
}

// ------------------------------ tile pipeline --------------------------------
// z = A(fp16) @ [Whi + Wlo/2048]^T : main fp32-acc + one fp16-acc correction.
// Tile 128(M)x64(N), 256 thr (4m x 2n warps, 32x32 each), KC=64,
// 3-stage cp.async pipeline (32KB/stage, 96KB/CTA -> 2 CTAs/SM).
// R4/R10-validated skeleton: DO NOT restructure the mainloop.
#define KC 64
#define OFF_AHI 0
#define OFF_BHI 16384
#define OFF_BLO 24576
#define STAGE_BYTES 32768
#define SMEM_TOTAL (3 * STAGE_BYTES)

__device__ __forceinline__ void load_chunk(
    uint32_t sb, int tid,
    const __half* __restrict__ a,
    const __half* __restrict__ bhi, const __half* __restrict__ blo,
    int r0, int n0, int K, int kc)
{
    const int kcol = kc * KC;
    #pragma unroll
    for (int i = 0; i < 4; ++i) {              // A: 128 rows x 8 chunks of 16B
        int q = tid + i * 256;
        int row = q >> 3, jj = q & 7;
        uint32_t so = swz(row * 128 + jj * 16);
        size_t ga = (size_t)(r0 + row) * K + kcol + jj * 8;
        cpa16(sb + OFF_AHI + so, a + ga);
    }
    #pragma unroll
    for (int i = 0; i < 2; ++i) {              // B: 64 rows x 8 chunks of 16B
        int q = tid + i * 256;
        int row = q >> 3, jj = q & 7;
        uint32_t so = swz(row * 128 + jj * 16);
        size_t gb = (size_t)(n0 + row) * K + kcol + jj * 8;
        cpa16(sb + OFF_BHI + so, bhi + gb);
        cpa16(sb + OFF_BLO + so, blo + gb);
    }
    CP_COMMIT();
}

__device__ __forceinline__ void load_b_chunk(
    uint32_t sb, int tid,
    const __half* __restrict__ bhi, const __half* __restrict__ blo,
    int n0, int K, int kc)
{
    const int kcol = kc * KC;
    #pragma unroll
    for (int i = 0; i < 2; ++i) {
        int q = tid + i * 256;
        int row = q >> 3, jj = q & 7;
        uint32_t so = swz(row * 128 + jj * 16);
        size_t gb = (size_t)(n0 + row) * K + kcol + jj * 8;
        cpa16(sb + OFF_BHI + so, bhi + gb);
        cpa16(sb + OFF_BLO + so, blo + gb);
    }
    CP_COMMIT();
}
__device__ __forceinline__ void load_a_chunk(
    uint32_t sb, int tid, const __half* __restrict__ a,
    int r0, int K, int kc)
{
    const int kcol = kc * KC;
    #pragma unroll
    for (int i = 0; i < 4; ++i) {
        int q = tid + i * 256;
        int row = q >> 3, jj = q & 7;
        uint32_t so = swz(row * 128 + jj * 16);
        size_t ga = (size_t)(r0 + row) * K + kcol + jj * 8;
        cpa16(sb + OFF_AHI + so, a + ga);
    }
    CP_COMMIT();
}

// One 128x64 tile: B preload -> dependency spin -> A preload -> mainloop ->
// fused LSTM / pred epilogue. Body identical to R15.
__device__ __forceinline__ void tile_work(
    const __half* __restrict__ a,
    const __half* __restrict__ bhi, const __half* __restrict__ blo,
    int K, const float* __restrict__ bias, int n, int mrow, int t,
    float* __restrict__ outp, __half* __restrict__ hout,
    uint32_t sbase, int tid, volatile int* depcnt, int deptarget)
{
    const int lane = tid & 31, w = tid >> 5;
    const int wm = w & 3, wn = w >> 2;             // 4 (m) x 2 (n) warps
    const int r0 = mrow * 128;
    const int n0 = n * 64;
    const int nch = K / KC;

    float dm[2][4][4];
    uint32_t dc[2][4][2];
    #pragma unroll
    for (int mi = 0; mi < 2; ++mi)
        #pragma unroll
        for (int nj = 0; nj < 4; ++nj) {
            #pragma unroll
            for (int q = 0; q < 4; ++q) dm[mi][nj][q] = 0.0f;
            dc[mi][nj][0] = 0u; dc[mi][nj][1] = 0u;
        }

    // B (constant weights) first; spin on producer row-block; then A.
    load_b_chunk(sbase + 0 * STAGE_BYTES, tid, bhi, blo, n0, K, 0);
    load_b_chunk(sbase + 1 * STAGE_BYTES, tid, bhi, blo, n0, K, 1);
    if (depcnt != nullptr) {
        if (tid == 0) {
            while (*depcnt < deptarget) __nanosleep(128);
            __threadfence();
        }
        __syncthreads();
    }
    load_a_chunk(sbase + 0 * STAGE_BYTES, tid, a, r0, K, 0);
    load_a_chunk(sbase + 1 * STAGE_BYTES, tid, a, r0, K, 1);

    const int lr = lane & 7, sel = lane >> 3;

    for (int kc = 0; kc < nch; ++kc) {
        if (kc + 2 < nch) {
            load_chunk(sbase + ((kc + 2) % 3) * STAGE_BYTES, tid,
                       a, bhi, blo, r0, n0, K, kc + 2);
            CP_WAIT(2);
        } else if (kc + 1 < nch) {
            CP_WAIT(1);
        } else {
            CP_WAIT(0);
        }
        __syncthreads();
        const uint32_t sb = sbase + (kc % 3) * STAGE_BYTES;

        #pragma unroll
        for (int k16 = 0; k16 < 4; ++k16) {
            uint32_t ah[2][4], bh[2][4], bl[2][4];
            #pragma unroll
            for (int mi = 0; mi < 2; ++mi) {
                int row = wm * 32 + mi * 16 + lr + (sel & 1) * 8;
                int kbe = (k16 * 16 + (sel >> 1) * 8) * 2;
                ldsm4(ah[mi], sb + OFF_AHI + swz(row * 128 + kbe));
            }
            #pragma unroll
            for (int njp = 0; njp < 2; ++njp) {
                int nrow = wn * 32 + njp * 16 + lr + (sel >> 1) * 8;
                int kbe = (k16 * 16 + (sel & 1) * 8) * 2;
                uint32_t off = swz(nrow * 128 + kbe);
                ldsm4(bh[njp], sb + OFF_BHI + off);
                ldsm4(bl[njp], sb + OFF_BLO + off);
            }
            #pragma unroll
            for (int mi = 0; mi < 2; ++mi)
                #pragma unroll
                for (int nj = 0; nj < 4; ++nj)
                    mma_f32(dm[mi][nj], ah[mi],
                            bh[nj >> 1][(nj & 1) * 2], bh[nj >> 1][(nj & 1) * 2 + 1]);
            #pragma unroll
            for (int mi = 0; mi < 2; ++mi)
                #pragma unroll
                for (int nj = 0; nj < 4; ++nj)
                    mma_f16(dc[mi][nj], ah[mi],
                            bl[nj >> 1][(nj & 1) * 2], bl[nj >> 1][(nj & 1) * 2 + 1]);
        }
        __syncthreads();
    }

    // ---------------- epilogue ----------------
    const bool isPred = (n0 >= GATES);
    const int qr = lane >> 2, t4 = lane & 3, qc = t4 * 2;
    const bool evenT = ((t4 & 1) == 0);
    const int etid = w * 16 + qr * 2 + (t4 >> 1);            // [0,128)
    const size_t cbase =
        (((size_t)mrow * 64 + (size_t)n) * 128 + (size_t)etid) * 16;

    #pragma unroll
    for (int mi = 0; mi < 2; ++mi) {
        #pragma unroll
        for (int half = 0; half < 2; ++half) {
            const int r = r0 + wm * 32 + mi * 16 + qr + half * 8;
            float4 ca4;
            float* ca = &ca4.x;
            if (!isPred && evenT)
                ca4 = __ldcg(reinterpret_cast<const float4*>(
                    g_cf + cbase + mi * 8 + half * 4));     // L2 (L1 not coherent in-kernel)
            #pragma unroll
            for (int nj = 0; nj < 4; ++nj) {
                const int c = wn * 32 + nj * 8 + qc;
                __half2 hc = *reinterpret_cast<__half2*>(&dc[mi][nj][half]);
                float zx = dm[mi][nj][half * 2 + 0]
                         + INV_LOSCALE * __half2float(__low2half(hc)) + bias[n0 + c];
                float zy = dm[mi][nj][half * 2 + 1]
                         + INV_LOSCALE * __half2float(__high2half(hc)) + bias[n0 + c + 1];
                if (isPred) {
                    float2 v = make_float2(zx, zy);
                    *reinterpret_cast<float2*>(
                        outp + (size_t)r * LDO + (size_t)(t - 1) * OUTU + (n0 - GATES) + c) = v;
                } else {
                    // even t4 holds (zi,zf), odd holds (zg,zo) of the same unit
                    float ox = __shfl_xor_sync(0xffffffffu, zx, 1);
                    float oy = __shfl_xor_sync(0xffffffffu, zy, 1);
                    if (evenT) {
                        const int u = ((n0 + c) >> 2);
                        const size_t off = (size_t)r * UNITS + u;
                        float ig = fsig(zx);
                        float fg = fsig(zy);
                        float gg = ftanh(ox);
                        float og = fsig(oy);
                        float cn = fg * ca[nj] + ig * gg;
                        ca[nj] = cn;
                        hout[off] = __float2half_rn(og * ftanh(cn));
                    }
                }
            }
            if (!isPred && evenT)
                __stcg(reinterpret_cast<float4*>(g_cf + cbase + mi * 8 + half * 4), ca4);
        }
    }
}

// ------------------------------ persistent kernel ----------------------------
__global__ __launch_bounds__(256, 2)
void pbgemm(float* __restrict__ outp)
{
    extern __shared__ __align__(1024) char smem[];
    const uint32_t sbase = smem_u32(smem);
    const int tid = threadIdx.x;
    __shared__ int s_id;

    for (;;) {
        if (tid == 0) s_id = atomicAdd(&g_ticket, 1);
        __syncthreads();
        const int id = s_id;
        if (id >= TTOTAL) break;

        const __half *A, *BH, *BL;
        const float* bias;
        __half* hout;
        int K, n, mrow, t;
        volatile int* dep = nullptr;
        int tgt = 0;

        if (id < T0) {                                   // step 0: gates only
            t = 0; mrow = id >> 6; n = id & 63;
            A = g_a0; BH = g_w0hi; BL = g_w0lo; K = K0;
            bias = g_b0i; hout = g_h1;
        } else if (id < T0 + 95 * TSZ) {                 // steps 1..95
            int q = id - T0;
            t = 1 + q / TSZ;
            int rem = q - (t - 1) * TSZ;
            if (rem < 1024) {                            // gates first (critical)
                mrow = rem >> 6; n = rem & 63;
            } else {                                     // preds trail the step
                int r2 = rem - 1024;
                mrow = r2 >> 2; n = 64 + (r2 & 3);
            }
            A = (t & 1) ? g_h1 : g_h0;                   // hb[t&1]
            hout = ((t + 1) & 1) ? g_h1 : g_h0;          // hb[(t+1)&1]
            BH = g_wthi; BL = g_wtlo; K = UNITS; bias = g_bcd;
            dep = (volatile int*)&g_cnt[(t - 1) * 16 + mrow];
            tgt = 64;                                    // gate tiles only
        } else {                                         // final pred_95 tiles
            int rem = id - (T0 + 95 * TSZ);
            t = STEPS; mrow = rem >> 2; n = 64 + (rem & 3);
            A = g_h0;                                    // h_96 = hb[0]
            hout = g_h1;                                 // unused (pred only)
            BH = g_wthi; BL = g_wtlo; K = UNITS; bias = g_bcd;
            dep = (volatile int*)&g_cnt[95 * 16 + mrow];
            tgt = 64;
        }

        tile_work(A, BH, BL, K, bias, n, mrow, t, outp, hout,
                  sbase, tid, dep, tgt);

        __threadfence();
        __syncthreads();
        if (tid == 0 && t < STEPS && n < 64)             // gate tiles signal
            atomicAdd(&g_cnt[t * 16 + mrow], 1);
    }
}

// ------------------------------ prep stage 1 ---------------------------------
// Concurrent, mutually independent: fp32 GEMM (g_Wcd cols 0..4095), combined
// bias, copy_wd (g_Wcd cols 4096+). GEMM blocks first for early scheduling.
#define PG_GEMM 256
#define PG_BIAS 17
#define PG_CW 1024
#define PG_TOTAL (PG_GEMM + PG_BIAS + PG_CW)

__global__ __launch_bounds__(256)
void prep_gemm(const float* __restrict__ Wk, const float* __restrict__ Wr,
               const float* __restrict__ b, const float* __restrict__ Wd,
               const float* __restrict__ bd) {
    __shared__ float As[8][128];
    __shared__ float Bs[8][128];
    const int blk = blockIdx.x;
    const int tid = threadIdx.x;

    if (blk < PG_GEMM) {
        // g_Wcd[:,0:4096] = Wd[1024,256] @ Wk[256,4096] + Wr
        const int tx = tid & 15, ty = tid >> 4;
        const int col0 = (blk & 31) * 128, row0 = (blk >> 5) * 128;
        float acc[8][8];
        #pragma unroll
        for (int i = 0; i < 8; ++i)
            #pragma unroll
            for (int j = 0; j < 8; ++j) acc[i][j] = 0.0f;
        const int arow = tid >> 1, acol = (tid & 1) << 2;
        const int brow = tid >> 5, bcol = (tid & 31) << 2;
        const float* Arow = Wd + (size_t)(row0 + arow) * OUTU + acol;
        const float* Brow = Wk + (size_t)brow * GATES + col0 + bcol;
        for (int k0 = 0; k0 < 256; k0 += 8) {
            float4 av = *reinterpret_cast<const float4*>(Arow + k0);
            float4 bv = *reinterpret_cast<const float4*>(Brow + (size_t)k0 * GATES);
            As[acol + 0][arow] = av.x; As[acol + 1][arow] = av.y;
            As[acol + 2][arow] = av.z; As[acol + 3][arow] = av.w;
            *reinterpret_cast<float4*>(&Bs[brow][bcol]) = bv;
            __syncthreads();
            #pragma unroll
            for (int k = 0; k < 8; ++k) {
                float a[8], bb[8];
                #pragma unroll
                for (int i = 0; i < 8; ++i) a[i] = As[k][ty * 8 + i];
                #pragma unroll
                for (int j = 0; j < 8; ++j) bb[j] = Bs[k][tx * 8 + j];
                #pragma unroll
                for (int i = 0; i < 8; ++i)
                    #pragma unroll
                    for (int j = 0; j < 8; ++j)
                        acc[i][j] = fmaf(a[i], bb[j], acc[i][j]);
            }
            __syncthreads();
        }
        const int gcol = col0 + tx * 8;
        #pragma unroll
        for (int i = 0; i < 8; ++i) {
            int r = row0 + ty * 8 + i;
            #pragma unroll
            for (int j = 0; j < 8; j += 4) {
                float4 v = make_float4(acc[i][j], acc[i][j+1], acc[i][j+2], acc[i][j+3]);
                float4 a4 = *reinterpret_cast<const float4*>(
                    Wr + (size_t)r * GATES + gcol + j);
                v.x += a4.x; v.y += a4.y; v.z += a4.z; v.w += a4.w;
                *reinterpret_cast<float4*>(g_Wcd + (size_t)r * NCOMB + gcol + j) = v;
            }
        }
    } else if (blk < PG_GEMM + PG_BIAS) {
        int j = (blk - PG_GEMM) * 256 + tid;
        if (j < GATES) {
            float s = b[j];
            #pragma unroll 4
            for (int k = 0; k < 256; ++k)
                s += bd[k] * Wk[(size_t)k * GATES + j];
            g_bcd[icol(j)] = s;
            g_b0i[icol(j)] = b[j];
        } else if (j < NCOMB) {
            g_bcd[j] = bd[j - GATES];
        }
    } else {
        int idx = (blk - PG_GEMM - PG_BIAS) * 256 + tid;
        if (idx < UNITS * OUTU) {
            int r = idx / OUTU, c = idx % OUTU;
            g_Wcd[(size_t)r * NCOMB + GATES + c] = Wd[idx];
        }
    }
}

// ------------------------------ prep stage 2 (splits) ------------------------
#define NB_WS 17408
#define NB_W0 20480
#define NB_A0 10240
#define NB_CI 8192
__global__ void prep_splits(const float* __restrict__ Wk, const float* __restrict__ Wr,
                            const float* __restrict__ x0, const float* __restrict__ h0,
                            const float* __restrict__ c0) {
    int blk = blockIdx.x;
    if (blk < NB_WS) {
        int idx = blk * 256 + threadIdx.x;            // over UNITS*NCOMB
        int k = idx / NCOMB, n = idx - k * NCOMB;
        float v = g_Wcd[idx];
        __half hi = __float2half_rn(v);
        size_t o = (size_t)icol(n) * UNITS + k;
        g_wthi[o] = hi;
        g_wtlo[o] = __float2half_rn((v - __half2float(hi)) * LOSCALE);
    } else if (blk < NB_WS + NB_W0) {
        int idx = (blk - NB_WS) * 256 + threadIdx.x;  // over GATES*K0
        int n = idx & (GATES - 1);
        int k = idx >> 12;
        float v = (k < 256) ? Wk[(size_t)k * GATES + n]
                            : Wr[(size_t)(k - 256) * GATES + n];
        __half hi = __float2half_rn(v);
        size_t o = (size_t)icol(n) * K0 + k;
        g_w0hi[o] = hi;
        g_w0lo[o] = __float2half_rn((v - __half2float(hi)) * LOSCALE);
    } else if (blk < NB_WS + NB_W0 + NB_A0) {
        int idx = (blk - NB_WS - NB_W0) * 256 + threadIdx.x;  // over BATCH*K0
        int r = idx / K0, k = idx - r * K0;
        float v = (k < 256) ? x0[(size_t)r * 256 + k] : h0[(size_t)r * UNITS + (k - 256)];
        g_a0[idx] = __float2half_rn(v);
    } else {
        int L = (blk - NB_WS - NB_W0 - NB_A0) * 256 + threadIdx.x;  // over BATCH*UNITS
        int mt = L >> 17;            // 64 nt * 2048 per m-tile
        int rem = L & 131071;
        int nt = rem >> 11;          // 2048 per n-tile
        int rem2 = rem & 2047;
        int etid = rem2 >> 4, pos = rem2 & 15;
        int ww = etid >> 4, q = etid & 15;
        int qr = q >> 1, th = q & 1;
        int wm = ww & 3, wn = ww >> 2;
        int mi = pos >> 3, half = (pos >> 2) & 1, nj = pos & 3;
        int r = mt * 128 + wm * 32 + mi * 16 + qr + half * 8;
        int u = nt * 16 + wn * 8 + nj * 2 + th;
        g_cf[L] = c0[(size_t)r * UNITS + u];
    }
}

// ------------------------------ launch ---------------------------------------
extern "C" void kernel_launch(void* const* d_in, const int* in_sizes, int n_in,
                              void* d_out, int out_size) {
    const float* x0 = (const float*)d_in[0];
    const float* h0 = (const float*)d_in[1];
    const float* c0 = (const float*)d_in[2];
    const float* Wk = (const float*)d_in[3];
    const float* Wr = (const float*)d_in[4];
    const float* b  = (const float*)d_in[5];
    const float* Wd = (const float*)d_in[6];
    const float* bd = (const float*)d_in[7];
    float* out = (float*)d_out;

    cudaFuncSetAttribute(pbgemm, cudaFuncAttributeMaxDynamicSharedMemorySize, SMEM_TOTAL);

    int *pTicket, *pCnt;
    cudaGetSymbolAddress((void**)&pTicket, g_ticket);
    cudaGetSymbolAddress((void**)&pCnt, g_cnt);

    // reset persistent-schedule state (graph-replay-safe, deterministic)
    cudaMemsetAsync(pTicket, 0, sizeof(int), 0);
    cudaMemsetAsync(pCnt, 0, STEPS * 16 * sizeof(int), 0);

    // prep stage 1: GEMM + bias + copy_wd, one concurrent launch
    prep_gemm<<<PG_TOTAL, 256>>>(Wk, Wr, b, Wd, bd);
    // prep stage 2: wsplit | w0split | a0split | c_init, full-chip concurrent
    prep_splits<<<NB_WS + NB_W0 + NB_A0 + NB_CI, 256>>>(Wk, Wr, x0, h0, c0);

    // all 97 steps in ONE persistent launch (ticket + per-(step,mrow) deps)
    pbgemm<<<NCTAS, 256, SMEM_TOTAL>>>(out);
}